// round 14
// baseline (speedup 1.0000x reference)
#include <cuda_runtime.h>
#include <math.h>

#define T_   2048
#define BK   64
#define H_   16
#define N_   64
#define TB   (T_*BK)
#define NC   64
#define CH   32

typedef unsigned long long ULL;

// -------- device scratch (static; b-major) --------
__device__ float  g_C  [(size_t)TB*N_];       // 33.5 MB  C[b][t][n]
__device__ float2 g_yD [(size_t)TB*H_];       // (y_local+du, D)[b][t][h]
__device__ float  g_end [NC*BK*H_*N_];        // 16.8 MB
__device__ float  g_init[NC*BK*H_*N_];        // 16.8 MB
__device__ float  g_V[64*H_];
__device__ float  g_g0[H_*N_];

__device__ __forceinline__ ULL pack2(float x) {
    ULL r; asm("mov.b64 %0, {%1, %1};" : "=l"(r) : "f"(x)); return r;
}
__device__ __forceinline__ void fma2(ULL& d, ULL a, ULL b) {
    asm("fma.rn.f32x2 %0, %1, %2, %0;" : "+l"(d) : "l"(a), "l"(b));
}
__device__ __forceinline__ void mul2(ULL& d, ULL a, ULL b) {
    asm("mul.rn.f32x2 %0, %1, %2;" : "=l"(d) : "l"(a), "l"(b));
}
__device__ __forceinline__ float2 unpack2(ULL v) {
    float lo, hi;
    asm("mov.b64 {%0, %1}, %2;" : "=f"(lo), "=f"(hi) : "l"(v));
    return make_float2(lo, hi);
}

// smem layout (float offsets), 69248 B -> 3 CTAs/SM (207.7 KB)
#define OFF_WB  0                       // [64][64]
#define OFF_WC  4096                    // [64][64]
#define OFF_V   8192                    // [64][16]
#define OFF_O   9216                    // [32 t][68]
#define OFF_RW  (OFF_O + 32*68)         // 11392, [32]
#define OFF_B   (OFF_RW + 32)           // 11424, [32 t][68]
#define OFF_C   (OFF_B + 32*68)         // 13600, [32 t][68]
#define OFF_S   (OFF_C + 32*68)         // 15776, [32 t][16 h]
#define OFF_DEC (OFF_S + 512)           // 16288, [32 t][16 h]
#define OFF_DU  (OFF_DEC + 512)         // 16800, [32 t][16 h]
#define MEGA_SMEM ((OFF_DU + 512) * 4)  // 69248 bytes

// ---------------------------------------------------------------------------
__global__ void prep_kernel(const float* __restrict__ W_in,
                            const float* __restrict__ W_out,
                            const float* __restrict__ init_state) {
    int tid = blockIdx.x * blockDim.x + threadIdx.x;
    if (tid < 64 * H_) {
        int o = tid >> 4, h = tid & 15;
        float acc = 0.f;
        #pragma unroll 8
        for (int p = 0; p < 64; p++)
            acc = fmaf(W_in[o*1024 + h*64 + p], W_out[h*64 + p], acc);
        g_V[o*H_ + h] = acc;
    } else if (tid < 64*H_ + H_*N_) {
        int i = tid - 64*H_;
        int h = i >> 6, n = i & 63;
        float acc = 0.f;
        #pragma unroll 8
        for (int p = 0; p < 64; p++)
            acc = fmaf(init_state[(h*64 + p)*64 + n], W_out[h*64 + p], acc);
        g_g0[i] = acc;
    }
}

// ---------------------------------------------------------------------------
// mega: CTA = (b, 32-t chunk), 3 CTAs/SM. GEMM: warps 0-3 -> B, 4-7 -> C;
// warp tile 16t x 32c, thread tile 2t x 8c (strided t). V/sd: thread =
// (t = tid>>3, 2 heads), scalar broadcast A loads. Scan: 4 warps; warp hg
// owns heads hg*4..+3, lane owns n-pair 2*lane (fma2-packed); 8-step
// window-transposed butterfly (R11 scan, 4 windows).
// ---------------------------------------------------------------------------
__global__ void __launch_bounds__(256, 3)
mega_kernel(const float* __restrict__ obs,
            const float* __restrict__ reward,
            const float* __restrict__ W_B,
            const float* __restrict__ W_C,
            const float* __restrict__ W_dt,
            const float* __restrict__ dt_bias,
            const float* __restrict__ A_log,
            const float* __restrict__ Dv) {
    extern __shared__ float sm[];
    float* sWB  = sm + OFF_WB;
    float* sWC  = sm + OFF_WC;
    float* sV   = sm + OFF_V;
    float* sO   = sm + OFF_O;
    float* sRw  = sm + OFF_RW;
    float* sB   = sm + OFF_B;
    float* sC   = sm + OFF_C;
    float* sS   = sm + OFF_S;
    float* sDec = sm + OFF_DEC;
    float* sDu  = sm + OFF_DU;

    int b = blockIdx.x & 63, c = blockIdx.x >> 6;
    int tid = threadIdx.x;
    int w = tid >> 5, lane = tid & 31;
    size_t bT = (size_t)b * T_;
    int t0c = c * CH;

    // ---- stage weights + V + obs + reward ----
    #pragma unroll
    for (int i = 0; i < 4; i++) {
        ((float4*)sWB)[tid + 256*i] = ((const float4*)W_B)[tid + 256*i];
        ((float4*)sWC)[tid + 256*i] = ((const float4*)W_C)[tid + 256*i];
    }
    ((float4*)sV)[tid] = ((const float4*)g_V)[tid];
    {
        int cc = (tid & 15) * 4;
        #pragma unroll
        for (int i = 0; i < 2; i++) {
            int f  = tid + 256*i;
            int tt = f >> 4;
            float4 v = *(const float4*)(obs + ((size_t)(t0c + tt)*64 + b)*64 + cc);
            *(float4*)&sO[tt*68 + cc] = v;
        }
        if (tid < 32) sRw[tid] = reward[(t0c + tid)*64 + b];
    }
    __syncthreads();

    // ---- main GEMM: B warps 0-3, C warps 4-7; warp tile 16t x 32c ----
    {
        bool isB = (w < 4);
        int wl = isB ? w : w - 4;
        int tbase   = (wl >> 1) * 16;
        int colbase = (wl & 1) * 32;
        int cx = lane & 3;          // 4 col-groups x 8 cols
        int tg = lane >> 2;         // 8 t-groups; lane's t = tbase + tg + 8i
        const float* sW = isB ? sWB : sWC;

        ULL acc[2][4];
        #pragma unroll
        for (int i = 0; i < 2; i++)
            #pragma unroll
            for (int j = 0; j < 4; j++) acc[i][j] = 0ull;

        #pragma unroll 2
        for (int k4 = 0; k4 < 16; k4++) {
            float4 av[2];
            #pragma unroll
            for (int i = 0; i < 2; i++)
                av[i] = *(const float4*)&sO[(tbase + tg + 8*i)*68 + k4*4];
            #pragma unroll
            for (int kk = 0; kk < 4; kk++) {
                int k = k4*4 + kk;
                ulonglong2 wA = *(const ulonglong2*)&sW[k*64 + colbase + cx*8];
                ulonglong2 wB = *(const ulonglong2*)&sW[k*64 + colbase + cx*8 + 4];
                #pragma unroll
                for (int i = 0; i < 2; i++) {
                    float a = (kk == 0) ? av[i].x : (kk == 1) ? av[i].y
                            : (kk == 2) ? av[i].z : av[i].w;
                    ULL ap = pack2(a);
                    fma2(acc[i][0], ap, wA.x);
                    fma2(acc[i][1], ap, wA.y);
                    fma2(acc[i][2], ap, wB.x);
                    fma2(acc[i][3], ap, wB.y);
                }
            }
        }

        // epilogue: STS to padded tile (+ global C for scan3)
        float* sT = isB ? sB : sC;
        #pragma unroll
        for (int i = 0; i < 2; i++) {
            int t = tbase + tg + 8*i;
            ulonglong2 q0 = make_ulonglong2(acc[i][0], acc[i][1]);
            ulonglong2 q1 = make_ulonglong2(acc[i][2], acc[i][3]);
            *(ulonglong2*)&sT[t*68 + colbase + cx*8]     = q0;
            *(ulonglong2*)&sT[t*68 + colbase + cx*8 + 4] = q1;
            if (!isB) {
                float* gp = g_C + (bT + t0c + t)*64 + colbase + cx*8;
                *(ulonglong2*)(gp)     = q0;
                *(ulonglong2*)(gp + 4) = q1;
            }
        }
    }

    // ---- V-GEMM + sd/du: thread owns (t = tid>>3, heads ho*2, ho*2+1) ----
    {
        int tV = tid >> 3, ho = tid & 7;
        float s0 = 0.f, s1 = 0.f;
        #pragma unroll 4
        for (int k = 0; k < 64; k++) {
            float a = sO[tV*68 + k];
            float2 v = *(const float2*)&sV[k*16 + ho*2];
            s0 = fmaf(a, v.x, s0);
            s1 = fmaf(a, v.y, s1);
        }
        float2 wd2 = __ldg((const float2*)(W_dt    + ho*2));
        float2 bs2 = __ldg((const float2*)(dt_bias + ho*2));
        float2 al2 = __ldg((const float2*)(A_log   + ho*2));
        float2 dv2 = __ldg((const float2*)(Dv      + ho*2));
        float rw = sRw[tV];
        float x0  = fmaf(rw, wd2.x, bs2.x);
        float dt0 = fmaxf(x0, 0.f) + __logf(1.f + __expf(-fabsf(x0)));
        float x1  = fmaf(rw, wd2.y, bs2.y);
        float dt1 = fmaxf(x1, 0.f) + __logf(1.f + __expf(-fabsf(x1)));
        *(float2*)&sS[tV*16 + ho*2]   = make_float2(dt0*s0, dt1*s1);
        *(float2*)&sDec[tV*16 + ho*2] = make_float2(__expf(dt0*(-__expf(al2.x))),
                                                    __expf(dt1*(-__expf(al2.y))));
        *(float2*)&sDu[tV*16 + ho*2]  = make_float2(dv2.x*s0, dv2.y*s1);
    }
    __syncthreads();

    // ---- scan: warps 0-3 only; warp hg owns heads hg*4..+3, lane owns
    //      n-pair {2*lane, 2*lane+1} (packed). No cross-warp exchange. ----
    if (w < 4) {
        int hg   = w;
        int n0   = 2*lane;
        int myj  = lane >> 3;          // which of the 4 heads this lane outputs
        int myq  = lane & 7;           // which timestep within the window
        int hOwn = hg*4 + myj;

        ULL gA = 0ull, gB2 = 0ull, gC2 = 0ull, gD = 0ull;
        float Dcar = 1.f;

        for (int win = 0; win < 4; win++) {
            float yv[32];
            float Dl = 1.f;
            #pragma unroll
            for (int q = 0; q < 8; q++) {
                int t = win*8 + q;
                ULL bv = *(const ULL*)&sB[t*68 + n0];
                ULL cv = *(const ULL*)&sC[t*68 + n0];
                float4 s4 = *(const float4*)&sS[t*16 + hg*4];
                float4 d4 = *(const float4*)&sDec[t*16 + hg*4];
                ULL u0, u1, u2, u3;
                mul2(u0, pack2(s4.x), bv); fma2(u0, gA,  pack2(d4.x)); gA  = u0;
                mul2(u1, pack2(s4.y), bv); fma2(u1, gB2, pack2(d4.y)); gB2 = u1;
                mul2(u2, pack2(s4.z), bv); fma2(u2, gC2, pack2(d4.z)); gC2 = u2;
                mul2(u3, pack2(s4.w), bv); fma2(u3, gD,  pack2(d4.w)); gD  = u3;
                ULL y0, y1, y2, y3;
                mul2(y0, gA,  cv); mul2(y1, gB2, cv);
                mul2(y2, gC2, cv); mul2(y3, gD,  cv);
                float2 f0 = unpack2(y0), f1 = unpack2(y1);
                float2 f2 = unpack2(y2), f3 = unpack2(y3);
                yv[q]      = f0.x + f0.y;
                yv[8 + q]  = f1.x + f1.y;
                yv[16 + q] = f2.x + f2.y;
                yv[24 + q] = f3.x + f3.y;
                float dOwn = sDec[t*16 + hOwn];
                if (q <= myq) Dl *= dOwn;
            }
            // 32-lane transposed butterfly: lane L ends with the 64-n sum for
            // (h = hg*4 + (L>>3), t = win*8 + (L&7))
            #pragma unroll
            for (int s = 16; s >= 1; s >>= 1) {
                bool hi = (lane & s) != 0;
                #pragma unroll
                for (int j = 0; j < s; j++) {
                    float snd = hi ? yv[j] : yv[j + s];
                    float rcv = __shfl_xor_sync(0xffffffffu, snd, s);
                    yv[j] = (hi ? yv[j + s] : yv[j]) + rcv;
                }
            }
            int t = win*8 + myq;
            float du = sDu[t*16 + hOwn];
            g_yD[(bT + t0c + t)*16 + hOwn] = make_float2(yv[0] + du, Dcar * Dl);
            float Dfull = __shfl_sync(0xffffffffu, Dl, (lane & 24) | 7);
            Dcar *= Dfull;
        }

        // chunk-final states (packed n-pairs)
        int e = ((c*64 + b)*16 + hg*4)*64 + n0;
        *(float2*)&g_end[e]       = unpack2(gA);
        *(float2*)&g_end[e + 64]  = unpack2(gB2);
        *(float2*)&g_end[e + 128] = unpack2(gC2);
        *(float2*)&g_end[e + 192] = unpack2(gD);
    }
}

// ---------------------------------------------------------------------------
// scan2: stitch 64 chunk initial states per (b,h). P staged via smem;
// e1/e2 ring prefetch (depth 4).
// ---------------------------------------------------------------------------
__global__ void scan2_kernel() {
    __shared__ float sP2[8][64];
    int w = threadIdx.x >> 5, lane = threadIdx.x & 31;
    int chain = blockIdx.x * 8 + w;
    int h = chain & 15, b = chain >> 4;

    // stage decay products P[0..NC-2] (P[j] closes chunk j+1's init)
    {
        int j0 = lane, j1 = lane + 32;
        if (j0 < NC-1)
            sP2[w][j0] = g_yD[((size_t)b*T_ + (j0+1)*CH - 1)*16 + h].y;
        if (j1 < NC-1)
            sP2[w][j1] = g_yD[((size_t)b*T_ + (j1+1)*CH - 1)*16 + h].y;
    }
    __syncwarp();

    float g1 = g_g0[h*64 + lane];
    float g2 = g_g0[h*64 + lane + 32];
    int gi0 = ((0*64 + b)*16 + h)*64;
    g_init[gi0 + lane]      = g1;
    g_init[gi0 + lane + 32] = g2;

    float e1[4], e2[4];
    #pragma unroll
    for (int j = 0; j < 4; j++) {
        int e = ((j*64 + b)*16 + h)*64;
        e1[j] = g_end[e + lane];
        e2[j] = g_end[e + lane + 32];
    }

    for (int c = 1; c < NC; c++) {
        int s = (c-1) & 3;
        float P = sP2[w][c-1];
        g1 = fmaf(g1, P, e1[s]);
        g2 = fmaf(g2, P, e2[s]);
        int gio = ((c*64 + b)*16 + h)*64;
        g_init[gio + lane]      = g1;
        g_init[gio + lane + 32] = g2;
        int jn = c + 3;
        if (jn <= NC-2) {
            int e = ((jn*64 + b)*16 + h)*64;
            e1[s] = g_end[e + lane];
            e2[s] = g_end[e + lane + 32];
        }
    }
}

// ---------------------------------------------------------------------------
// scan3: correction + head-sum + output. Block per (b,chunk), 8 warps x 4 t;
// per-row loads software-pipelined.
// ---------------------------------------------------------------------------
__global__ void scan3_kernel(float* __restrict__ out, int out_size) {
    int b = blockIdx.x & 63, c = blockIdx.x >> 6;
    int lane = threadIdx.x & 31;
    int w    = threadIdx.x >> 5;

    float gi1[16], gi2[16];
    #pragma unroll
    for (int h = 0; h < 16; h++) {
        int gi = ((c*64 + b)*16 + h)*64;
        gi1[h] = g_init[gi + lane];
        gi2[h] = g_init[gi + lane + 32];
    }

    size_t bT = (size_t)b*T_;
    int tbase = c*CH + w*4;

    // prologue: load row 0
    float c1 = g_C[(bT + tbase)*64 + lane];
    float c2 = g_C[(bT + tbase)*64 + lane + 32];
    float2 yD = make_float2(0.f, 0.f);
    if (lane < 16) yD = g_yD[(bT + tbase)*16 + lane];

    #pragma unroll
    for (int q = 0; q < 4; q++) {
        float c1n = 0.f, c2n = 0.f;
        float2 yDn = make_float2(0.f, 0.f);
        if (q < 3) {
            size_t rn = bT + tbase + q + 1;
            c1n = g_C[rn*64 + lane];
            c2n = g_C[rn*64 + lane + 32];
            if (lane < 16) yDn = g_yD[rn*16 + lane];
        }

        float acc = yD.x;
        #pragma unroll
        for (int h = 0; h < 16; h++) {
            float Dh = __shfl_sync(0xffffffffu, yD.y, h);
            acc = fmaf(Dh, fmaf(gi2[h], c2, gi1[h]*c1), acc);
        }
        acc += __shfl_xor_sync(0xffffffffu, acc, 16);
        acc += __shfl_xor_sync(0xffffffffu, acc, 8);
        acc += __shfl_xor_sync(0xffffffffu, acc, 4);
        acc += __shfl_xor_sync(0xffffffffu, acc, 2);
        acc += __shfl_xor_sync(0xffffffffu, acc, 1);
        if (lane == 0) {
            int idx = (tbase + q)*64 + b;
            for (int j = idx; j < out_size; j += TB) out[j] = acc;
        }
        c1 = c1n; c2 = c2n; yD = yDn;
    }
}

// ---------------------------------------------------------------------------
extern "C" void kernel_launch(void* const* d_in, const int* in_sizes, int n_in,
                              void* d_out, int out_size) {
    const float* obs     = (const float*)d_in[0];
    const float* reward  = (const float*)d_in[1];
    const float* W_in    = (const float*)d_in[2];
    const float* W_B     = (const float*)d_in[3];
    const float* W_C     = (const float*)d_in[4];
    const float* W_dt    = (const float*)d_in[5];
    const float* dt_b    = (const float*)d_in[6];
    const float* A_log   = (const float*)d_in[7];
    const float* Dv      = (const float*)d_in[8];
    const float* W_out   = (const float*)d_in[9];
    const float* init    = (const float*)d_in[10];
    float* out = (float*)d_out;

    cudaFuncSetAttribute(mega_kernel,
                         cudaFuncAttributeMaxDynamicSharedMemorySize, MEGA_SMEM);

    prep_kernel<<<8, 256>>>(W_in, W_out, init);
    mega_kernel<<<BK*NC, 256, MEGA_SMEM>>>(obs, reward, W_B, W_C,
                                           W_dt, dt_b, A_log, Dv);
    scan2_kernel<<<BK*H_/8, 256>>>();
    scan3_kernel<<<BK*NC, 256>>>(out, out_size);
}

// round 15
// speedup vs baseline: 1.1774x; 1.1774x over previous
#include <cuda_runtime.h>
#include <math.h>

#define T_   2048
#define BK   64
#define H_   16
#define N_   64
#define TB   (T_*BK)
#define NC   32
#define CH   64

typedef unsigned long long ULL;

// -------- device scratch (static; b-major) --------
__device__ float  g_C  [(size_t)TB*N_];       // 33.5 MB  C[b][t][n]
__device__ float2 g_yD [(size_t)TB*H_];       // (y_local+du, D)[b][t][h]
__device__ float  g_end [NC*BK*H_*N_];        // 8 MB
__device__ float  g_init[NC*BK*H_*N_];        // 8 MB
__device__ float  g_V[64*H_];
__device__ float  g_g0[H_*N_];
__device__ float  g_sink;

__device__ __forceinline__ ULL pack2(float x) {
    ULL r; asm("mov.b64 %0, {%1, %1};" : "=l"(r) : "f"(x)); return r;
}
__device__ __forceinline__ void fma2(ULL& d, ULL a, ULL b) {
    asm("fma.rn.f32x2 %0, %1, %2, %0;" : "+l"(d) : "l"(a), "l"(b));
}
__device__ __forceinline__ void mul2(ULL& d, ULL a, ULL b) {
    asm("mul.rn.f32x2 %0, %1, %2;" : "=l"(d) : "l"(a), "l"(b));
}
__device__ __forceinline__ float2 unpack2(ULL v) {
    float lo, hi;
    asm("mov.b64 {%0, %1}, %2;" : "=f"(lo), "=f"(hi) : "l"(v));
    return make_float2(lo, hi);
}

// smem layout (float offsets), ~101.6 KB -> 2 CTAs/SM
#define OFF_WB  0                       // [64][64]
#define OFF_WC  4096                    // [64][64]
#define OFF_V   8192                    // [64][16]
#define OFF_O   9216                    // [64 t][68]
#define OFF_RW  (OFF_O + 64*68)         // 13568, [64]
#define OFF_B   (OFF_RW + 64)           // 13632, [64 t][68]
#define OFF_C   (OFF_B + 64*68)         // 17984, [64 t][68]
#define OFF_S   (OFF_C + 64*68)         // 22336, [64 t][16 h]
#define OFF_DEC (OFF_S + 1024)          // 23360, [64 t][16 h]
#define OFF_DU  (OFF_DEC + 1024)        // 24384, [64 t][16 h]
#define MEGA_SMEM ((OFF_DU + 1024) * 4) // 101632 bytes

// ---------------------------------------------------------------------------
__global__ void prep_kernel(const float* __restrict__ W_in,
                            const float* __restrict__ W_out,
                            const float* __restrict__ init_state) {
    int tid = blockIdx.x * blockDim.x + threadIdx.x;
    if (tid < 64 * H_) {
        int o = tid >> 4, h = tid & 15;
        float acc = 0.f;
        #pragma unroll 8
        for (int p = 0; p < 64; p++)
            acc = fmaf(W_in[o*1024 + h*64 + p], W_out[h*64 + p], acc);
        g_V[o*H_ + h] = acc;
    } else if (tid < 64*H_ + H_*N_) {
        int i = tid - 64*H_;
        int h = i >> 6, n = i & 63;
        float acc = 0.f;
        #pragma unroll 8
        for (int p = 0; p < 64; p++)
            acc = fmaf(init_state[(h*64 + p)*64 + n], W_out[h*64 + p], acc);
        g_g0[i] = acc;
    }
}

__global__ void dummy_kernel() {
    if (threadIdx.x == 0 && blockIdx.x == 0) g_sink = 1.f;
}

// ---------------------------------------------------------------------------
// mega: R11 verbatim (measured 103.1 us). CTA = (b, 64-t chunk), 2 CTAs/SM.
// GEMM: warps 0-3 -> B, 4-7 -> C; warp tile 32t x 32c, thread tile 4t x 8c.
// V/sd: thread = (t, 4 heads), SCALAR broadcast A loads (conflict-free).
// Scan: 4 warps; warp hg owns heads hg*4..+3, lane owns n-pair 2*lane
// (fma2-packed); 8-step window-transposed butterfly.
// ---------------------------------------------------------------------------
__global__ void __launch_bounds__(256, 2)
mega_kernel(const float* __restrict__ obs,
            const float* __restrict__ reward,
            const float* __restrict__ W_B,
            const float* __restrict__ W_C,
            const float* __restrict__ W_dt,
            const float* __restrict__ dt_bias,
            const float* __restrict__ A_log,
            const float* __restrict__ Dv) {
    extern __shared__ float sm[];
    float* sWB  = sm + OFF_WB;
    float* sWC  = sm + OFF_WC;
    float* sV   = sm + OFF_V;
    float* sO   = sm + OFF_O;
    float* sRw  = sm + OFF_RW;
    float* sB   = sm + OFF_B;
    float* sC   = sm + OFF_C;
    float* sS   = sm + OFF_S;
    float* sDec = sm + OFF_DEC;
    float* sDu  = sm + OFF_DU;

    int b = blockIdx.x & 63, c = blockIdx.x >> 6;
    int tid = threadIdx.x;
    int w = tid >> 5, lane = tid & 31;
    size_t bT = (size_t)b * T_;
    int t0c = c * CH;

    // ---- stage weights + V + obs + reward ----
    #pragma unroll
    for (int i = 0; i < 4; i++) {
        ((float4*)sWB)[tid + 256*i] = ((const float4*)W_B)[tid + 256*i];
        ((float4*)sWC)[tid + 256*i] = ((const float4*)W_C)[tid + 256*i];
    }
    ((float4*)sV)[tid] = ((const float4*)g_V)[tid];
    {
        int cc = (tid & 15) * 4;
        #pragma unroll
        for (int i = 0; i < 4; i++) {
            int f  = tid + 256*i;
            int tt = f >> 4;
            float4 v = *(const float4*)(obs + ((size_t)(t0c + tt)*64 + b)*64 + cc);
            *(float4*)&sO[tt*68 + cc] = v;
        }
        if (tid < 64) sRw[tid] = reward[(t0c + tid)*64 + b];
    }
    __syncthreads();

    // ---- main GEMM: B warps 0-3, C warps 4-7; warp tile 32t x 32c ----
    {
        bool isB = (w < 4);
        int wl = isB ? w : w - 4;
        int tbase   = (wl >> 1) * 32;
        int colbase = (wl & 1) * 32;
        int cx = lane & 3;          // 4 col-groups x 8 cols
        int tg = lane >> 2;         // 8 t-groups; lane's t = tbase + tg + 8i
        const float* sW = isB ? sWB : sWC;

        ULL acc[4][4];
        #pragma unroll
        for (int i = 0; i < 4; i++)
            #pragma unroll
            for (int j = 0; j < 4; j++) acc[i][j] = 0ull;

        #pragma unroll 2
        for (int k4 = 0; k4 < 16; k4++) {
            float4 av[4];
            #pragma unroll
            for (int i = 0; i < 4; i++)
                av[i] = *(const float4*)&sO[(tbase + tg + 8*i)*68 + k4*4];
            #pragma unroll
            for (int kk = 0; kk < 4; kk++) {
                int k = k4*4 + kk;
                ulonglong2 wA = *(const ulonglong2*)&sW[k*64 + colbase + cx*8];
                ulonglong2 wB = *(const ulonglong2*)&sW[k*64 + colbase + cx*8 + 4];
                #pragma unroll
                for (int i = 0; i < 4; i++) {
                    float a = (kk == 0) ? av[i].x : (kk == 1) ? av[i].y
                            : (kk == 2) ? av[i].z : av[i].w;
                    ULL ap = pack2(a);
                    fma2(acc[i][0], ap, wA.x);
                    fma2(acc[i][1], ap, wA.y);
                    fma2(acc[i][2], ap, wB.x);
                    fma2(acc[i][3], ap, wB.y);
                }
            }
        }

        // epilogue: STS to padded tile (+ global C for scan3)
        float* sT = isB ? sB : sC;
        #pragma unroll
        for (int i = 0; i < 4; i++) {
            int t = tbase + tg + 8*i;
            ulonglong2 q0 = make_ulonglong2(acc[i][0], acc[i][1]);
            ulonglong2 q1 = make_ulonglong2(acc[i][2], acc[i][3]);
            *(ulonglong2*)&sT[t*68 + colbase + cx*8]     = q0;
            *(ulonglong2*)&sT[t*68 + colbase + cx*8 + 4] = q1;
            if (!isB) {
                float* gp = g_C + (bT + t0c + t)*64 + colbase + cx*8;
                *(ulonglong2*)(gp)     = q0;
                *(ulonglong2*)(gp + 4) = q1;
            }
        }
    }

    // ---- V-GEMM + sd/du: thread owns (t = tid>>2, heads ho*4..ho*4+3) ----
    {
        int tV = tid >> 2, ho = tid & 3;
        float s0[4] = {0.f, 0.f, 0.f, 0.f};
        #pragma unroll 4
        for (int k = 0; k < 64; k++) {
            float a = sO[tV*68 + k];
            float4 v0 = *(const float4*)&sV[k*16 + ho*4];
            s0[0] = fmaf(a, v0.x, s0[0]); s0[1] = fmaf(a, v0.y, s0[1]);
            s0[2] = fmaf(a, v0.z, s0[2]); s0[3] = fmaf(a, v0.w, s0[3]);
        }
        float4 wd4 = __ldg((const float4*)(W_dt    + ho*4));
        float4 bs4 = __ldg((const float4*)(dt_bias + ho*4));
        float4 al4 = __ldg((const float4*)(A_log   + ho*4));
        float4 dv4 = __ldg((const float4*)(Dv      + ho*4));
        float wd[4] = {wd4.x, wd4.y, wd4.z, wd4.w};
        float bs[4] = {bs4.x, bs4.y, bs4.z, bs4.w};
        float al[4] = {al4.x, al4.y, al4.z, al4.w};
        float dv[4] = {dv4.x, dv4.y, dv4.z, dv4.w};
        float rw = sRw[tV];
        float sv[4], dc[4], du[4];
        #pragma unroll
        for (int j = 0; j < 4; j++) {
            float x  = fmaf(rw, wd[j], bs[j]);
            float dt = fmaxf(x, 0.f) + __logf(1.f + __expf(-fabsf(x)));
            dc[j] = __expf(dt * (-__expf(al[j])));
            sv[j] = dt * s0[j];
            du[j] = dv[j] * s0[j];
        }
        *(float4*)&sS[tV*16 + ho*4]   = make_float4(sv[0], sv[1], sv[2], sv[3]);
        *(float4*)&sDec[tV*16 + ho*4] = make_float4(dc[0], dc[1], dc[2], dc[3]);
        *(float4*)&sDu[tV*16 + ho*4]  = make_float4(du[0], du[1], du[2], du[3]);
    }
    __syncthreads();

    // ---- scan: warps 0-3 only; warp hg owns heads hg*4..+3, lane owns
    //      n-pair {2*lane, 2*lane+1} (packed). No cross-warp exchange. ----
    if (w < 4) {
        int hg   = w;
        int n0   = 2*lane;
        int myj  = lane >> 3;          // which of the 4 heads this lane outputs
        int myq  = lane & 7;           // which timestep within the window
        int hOwn = hg*4 + myj;

        ULL gA = 0ull, gB2 = 0ull, gC2 = 0ull, gD = 0ull;
        float Dcar = 1.f;

        for (int win = 0; win < 8; win++) {
            float yv[32];
            float Dl = 1.f;
            #pragma unroll
            for (int q = 0; q < 8; q++) {
                int t = win*8 + q;
                ULL bv = *(const ULL*)&sB[t*68 + n0];
                ULL cv = *(const ULL*)&sC[t*68 + n0];
                float4 s4 = *(const float4*)&sS[t*16 + hg*4];
                float4 d4 = *(const float4*)&sDec[t*16 + hg*4];
                ULL u0, u1, u2, u3;
                mul2(u0, pack2(s4.x), bv); fma2(u0, gA,  pack2(d4.x)); gA  = u0;
                mul2(u1, pack2(s4.y), bv); fma2(u1, gB2, pack2(d4.y)); gB2 = u1;
                mul2(u2, pack2(s4.z), bv); fma2(u2, gC2, pack2(d4.z)); gC2 = u2;
                mul2(u3, pack2(s4.w), bv); fma2(u3, gD,  pack2(d4.w)); gD  = u3;
                ULL y0, y1, y2, y3;
                mul2(y0, gA,  cv); mul2(y1, gB2, cv);
                mul2(y2, gC2, cv); mul2(y3, gD,  cv);
                float2 f0 = unpack2(y0), f1 = unpack2(y1);
                float2 f2 = unpack2(y2), f3 = unpack2(y3);
                yv[q]      = f0.x + f0.y;
                yv[8 + q]  = f1.x + f1.y;
                yv[16 + q] = f2.x + f2.y;
                yv[24 + q] = f3.x + f3.y;
                float dOwn = sDec[t*16 + hOwn];
                if (q <= myq) Dl *= dOwn;
            }
            // 32-lane transposed butterfly: lane L ends with the 64-n sum for
            // (h = hg*4 + (L>>3), t = win*8 + (L&7))
            #pragma unroll
            for (int s = 16; s >= 1; s >>= 1) {
                bool hi = (lane & s) != 0;
                #pragma unroll
                for (int j = 0; j < s; j++) {
                    float snd = hi ? yv[j] : yv[j + s];
                    float rcv = __shfl_xor_sync(0xffffffffu, snd, s);
                    yv[j] = (hi ? yv[j + s] : yv[j]) + rcv;
                }
            }
            int t = win*8 + myq;
            float du = sDu[t*16 + hOwn];
            g_yD[(bT + t0c + t)*16 + hOwn] = make_float2(yv[0] + du, Dcar * Dl);
            float Dfull = __shfl_sync(0xffffffffu, Dl, (lane & 24) | 7);
            Dcar *= Dfull;
        }

        // chunk-final states (packed n-pairs)
        int e = ((c*64 + b)*16 + hg*4)*64 + n0;
        *(float2*)&g_end[e]       = unpack2(gA);
        *(float2*)&g_end[e + 64]  = unpack2(gB2);
        *(float2*)&g_end[e + 128] = unpack2(gC2);
        *(float2*)&g_end[e + 192] = unpack2(gD);
    }
}

// ---------------------------------------------------------------------------
// scan2: stitch 32 chunk initial states per (b,h). Ring prefetch (depth 4).
// ---------------------------------------------------------------------------
__global__ void scan2_kernel() {
    int chain = blockIdx.x * 8 + (threadIdx.x >> 5);
    int lane  = threadIdx.x & 31;
    int h = chain & 15, b = chain >> 4;

    float g1 = g_g0[h*64 + lane];
    float g2 = g_g0[h*64 + lane + 32];
    int gi0 = ((0*64 + b)*16 + h)*64;
    g_init[gi0 + lane]      = g1;
    g_init[gi0 + lane + 32] = g2;

    float P[NC-1];
    #pragma unroll
    for (int j = 0; j < NC-1; j++)
        P[j] = g_yD[((size_t)b*T_ + (j+1)*CH - 1)*16 + h].y;

    float e1[4], e2[4];
    #pragma unroll
    for (int j = 0; j < 4; j++) {
        int e = ((j*64 + b)*16 + h)*64;
        e1[j] = g_end[e + lane];
        e2[j] = g_end[e + lane + 32];
    }

    #pragma unroll
    for (int c = 1; c < NC; c++) {
        int s = (c-1) & 3;
        g1 = fmaf(g1, P[c-1], e1[s]);
        g2 = fmaf(g2, P[c-1], e2[s]);
        int gio = ((c*64 + b)*16 + h)*64;
        g_init[gio + lane]      = g1;
        g_init[gio + lane + 32] = g2;
        int jn = c + 3;
        if (jn <= NC-2) {
            int e = ((jn*64 + b)*16 + h)*64;
            e1[s] = g_end[e + lane];
            e2[s] = g_end[e + lane + 32];
        }
    }
}

// ---------------------------------------------------------------------------
// scan3: correction + head-sum + output. Block per (b,chunk), 8 warps x 8 t;
// per-row loads software-pipelined (prefetch row q+1 before computing row q).
// ---------------------------------------------------------------------------
__global__ void scan3_kernel(float* __restrict__ out, int out_size) {
    int b = blockIdx.x & 63, c = blockIdx.x >> 6;
    int lane = threadIdx.x & 31;
    int w    = threadIdx.x >> 5;

    float gi1[16], gi2[16];
    #pragma unroll
    for (int h = 0; h < 16; h++) {
        int gi = ((c*64 + b)*16 + h)*64;
        gi1[h] = g_init[gi + lane];
        gi2[h] = g_init[gi + lane + 32];
    }

    size_t bT = (size_t)b*T_;
    int tbase = c*CH + w*8;

    // prologue: load row 0
    float c1 = g_C[(bT + tbase)*64 + lane];
    float c2 = g_C[(bT + tbase)*64 + lane + 32];
    float2 yD = make_float2(0.f, 0.f);
    if (lane < 16) yD = g_yD[(bT + tbase)*16 + lane];

    #pragma unroll
    for (int q = 0; q < 8; q++) {
        // prefetch next row before computing this one
        float c1n = 0.f, c2n = 0.f;
        float2 yDn = make_float2(0.f, 0.f);
        if (q < 7) {
            size_t rn = bT + tbase + q + 1;
            c1n = g_C[rn*64 + lane];
            c2n = g_C[rn*64 + lane + 32];
            if (lane < 16) yDn = g_yD[rn*16 + lane];
        }

        float acc = yD.x;
        #pragma unroll
        for (int h = 0; h < 16; h++) {
            float Dh = __shfl_sync(0xffffffffu, yD.y, h);
            acc = fmaf(Dh, fmaf(gi2[h], c2, gi1[h]*c1), acc);
        }
        acc += __shfl_xor_sync(0xffffffffu, acc, 16);
        acc += __shfl_xor_sync(0xffffffffu, acc, 8);
        acc += __shfl_xor_sync(0xffffffffu, acc, 4);
        acc += __shfl_xor_sync(0xffffffffu, acc, 2);
        acc += __shfl_xor_sync(0xffffffffu, acc, 1);
        if (lane == 0) {
            int idx = (tbase + q)*64 + b;
            for (int j = idx; j < out_size; j += TB) out[j] = acc;
        }
        c1 = c1n; c2 = c2n; yD = yDn;
    }
}

// ---------------------------------------------------------------------------
extern "C" void kernel_launch(void* const* d_in, const int* in_sizes, int n_in,
                              void* d_out, int out_size) {
    const float* obs     = (const float*)d_in[0];
    const float* reward  = (const float*)d_in[1];
    const float* W_in    = (const float*)d_in[2];
    const float* W_B     = (const float*)d_in[3];
    const float* W_C     = (const float*)d_in[4];
    const float* W_dt    = (const float*)d_in[5];
    const float* dt_b    = (const float*)d_in[6];
    const float* A_log   = (const float*)d_in[7];
    const float* Dv      = (const float*)d_in[8];
    const float* W_out   = (const float*)d_in[9];
    const float* init    = (const float*)d_in[10];
    float* out = (float*)d_out;

    cudaFuncSetAttribute(mega_kernel,
                         cudaFuncAttributeMaxDynamicSharedMemorySize, MEGA_SMEM);

    prep_kernel<<<8, 256>>>(W_in, W_out, init);
    dummy_kernel<<<1, 32>>>();          // keep mega in the profiled slot (#4)
    dummy_kernel<<<1, 32>>>();
    mega_kernel<<<BK*NC, 256, MEGA_SMEM>>>(obs, reward, W_B, W_C,
                                           W_dt, dt_b, A_log, Dv);
    scan2_kernel<<<BK*H_/8, 256>>>();
    scan3_kernel<<<BK*NC, 256>>>(out, out_size);
}

// round 16
// speedup vs baseline: 1.2386x; 1.0520x over previous
#include <cuda_runtime.h>
#include <math.h>

#define T_   2048
#define BK   64
#define H_   16
#define N_   64
#define TB   (T_*BK)
#define NC   32
#define CH   64

typedef unsigned long long ULL;

// -------- device scratch (static; b-major) --------
__device__ float  g_C  [(size_t)TB*N_];       // 33.5 MB  C[b][t][n]
__device__ float2 g_yD [(size_t)TB*H_];       // (y_local+du, D)[b][t][h]
__device__ float  g_end [NC*BK*H_*N_];        // 8 MB
__device__ float  g_init[NC*BK*H_*N_];        // 8 MB
__device__ float  g_V[64*H_];
__device__ float  g_g0[H_*N_];

__device__ __forceinline__ ULL pack2(float x) {
    ULL r; asm("mov.b64 %0, {%1, %1};" : "=l"(r) : "f"(x)); return r;
}
__device__ __forceinline__ void fma2(ULL& d, ULL a, ULL b) {
    asm("fma.rn.f32x2 %0, %1, %2, %0;" : "+l"(d) : "l"(a), "l"(b));
}
__device__ __forceinline__ void mul2(ULL& d, ULL a, ULL b) {
    asm("mul.rn.f32x2 %0, %1, %2;" : "=l"(d) : "l"(a), "l"(b));
}
__device__ __forceinline__ float2 unpack2(ULL v) {
    float lo, hi;
    asm("mov.b64 {%0, %1}, %2;" : "=f"(lo), "=f"(hi) : "l"(v));
    return make_float2(lo, hi);
}

// smem layout (float offsets), ~101.6 KB -> 2 CTAs/SM
#define OFF_WB  0                       // [64][64]
#define OFF_WC  4096                    // [64][64]
#define OFF_V   8192                    // [64][16]
#define OFF_O   9216                    // [64 t][68]
#define OFF_RW  (OFF_O + 64*68)         // 13568, [64]
#define OFF_B   (OFF_RW + 64)           // 13632, [64 t][68]
#define OFF_C   (OFF_B + 64*68)         // 17984, [64 t][68]
#define OFF_S   (OFF_C + 64*68)         // 22336, [64 t][16 h]
#define OFF_DEC (OFF_S + 1024)          // 23360, [64 t][16 h]
#define OFF_DU  (OFF_DEC + 1024)        // 24384, [64 t][16 h]
#define MEGA_SMEM ((OFF_DU + 1024) * 4) // 101632 bytes

// ---------------------------------------------------------------------------
__global__ void prep_kernel(const float* __restrict__ W_in,
                            const float* __restrict__ W_out,
                            const float* __restrict__ init_state) {
    int tid = blockIdx.x * blockDim.x + threadIdx.x;
    if (tid < 64 * H_) {
        int o = tid >> 4, h = tid & 15;
        float acc = 0.f;
        #pragma unroll 8
        for (int p = 0; p < 64; p++)
            acc = fmaf(W_in[o*1024 + h*64 + p], W_out[h*64 + p], acc);
        g_V[o*H_ + h] = acc;
    } else if (tid < 64*H_ + H_*N_) {
        int i = tid - 64*H_;
        int h = i >> 6, n = i & 63;
        float acc = 0.f;
        #pragma unroll 8
        for (int p = 0; p < 64; p++)
            acc = fmaf(init_state[(h*64 + p)*64 + n], W_out[h*64 + p], acc);
        g_g0[i] = acc;
    }
}

// ---------------------------------------------------------------------------
// mega: R15 verbatim (measured 103.0 us). CTA = (b, 64-t chunk), 2 CTAs/SM.
// GEMM: warps 0-3 -> B, 4-7 -> C; warp tile 32t x 32c, thread tile 4t x 8c.
// V/sd: thread = (t, 4 heads), SCALAR broadcast A loads (conflict-free).
// Scan: 4 warps; warp hg owns heads hg*4..+3, lane owns n-pair 2*lane
// (fma2-packed); 8-step window-transposed butterfly.
// ---------------------------------------------------------------------------
__global__ void __launch_bounds__(256, 2)
mega_kernel(const float* __restrict__ obs,
            const float* __restrict__ reward,
            const float* __restrict__ W_B,
            const float* __restrict__ W_C,
            const float* __restrict__ W_dt,
            const float* __restrict__ dt_bias,
            const float* __restrict__ A_log,
            const float* __restrict__ Dv) {
    extern __shared__ float sm[];
    float* sWB  = sm + OFF_WB;
    float* sWC  = sm + OFF_WC;
    float* sV   = sm + OFF_V;
    float* sO   = sm + OFF_O;
    float* sRw  = sm + OFF_RW;
    float* sB   = sm + OFF_B;
    float* sC   = sm + OFF_C;
    float* sS   = sm + OFF_S;
    float* sDec = sm + OFF_DEC;
    float* sDu  = sm + OFF_DU;

    int b = blockIdx.x & 63, c = blockIdx.x >> 6;
    int tid = threadIdx.x;
    int w = tid >> 5, lane = tid & 31;
    size_t bT = (size_t)b * T_;
    int t0c = c * CH;

    // ---- stage weights + V + obs + reward ----
    #pragma unroll
    for (int i = 0; i < 4; i++) {
        ((float4*)sWB)[tid + 256*i] = ((const float4*)W_B)[tid + 256*i];
        ((float4*)sWC)[tid + 256*i] = ((const float4*)W_C)[tid + 256*i];
    }
    ((float4*)sV)[tid] = ((const float4*)g_V)[tid];
    {
        int cc = (tid & 15) * 4;
        #pragma unroll
        for (int i = 0; i < 4; i++) {
            int f  = tid + 256*i;
            int tt = f >> 4;
            float4 v = *(const float4*)(obs + ((size_t)(t0c + tt)*64 + b)*64 + cc);
            *(float4*)&sO[tt*68 + cc] = v;
        }
        if (tid < 64) sRw[tid] = reward[(t0c + tid)*64 + b];
    }
    __syncthreads();

    // ---- main GEMM: B warps 0-3, C warps 4-7; warp tile 32t x 32c ----
    {
        bool isB = (w < 4);
        int wl = isB ? w : w - 4;
        int tbase   = (wl >> 1) * 32;
        int colbase = (wl & 1) * 32;
        int cx = lane & 3;          // 4 col-groups x 8 cols
        int tg = lane >> 2;         // 8 t-groups; lane's t = tbase + tg + 8i
        const float* sW = isB ? sWB : sWC;

        ULL acc[4][4];
        #pragma unroll
        for (int i = 0; i < 4; i++)
            #pragma unroll
            for (int j = 0; j < 4; j++) acc[i][j] = 0ull;

        #pragma unroll 2
        for (int k4 = 0; k4 < 16; k4++) {
            float4 av[4];
            #pragma unroll
            for (int i = 0; i < 4; i++)
                av[i] = *(const float4*)&sO[(tbase + tg + 8*i)*68 + k4*4];
            #pragma unroll
            for (int kk = 0; kk < 4; kk++) {
                int k = k4*4 + kk;
                ulonglong2 wA = *(const ulonglong2*)&sW[k*64 + colbase + cx*8];
                ulonglong2 wB = *(const ulonglong2*)&sW[k*64 + colbase + cx*8 + 4];
                #pragma unroll
                for (int i = 0; i < 4; i++) {
                    float a = (kk == 0) ? av[i].x : (kk == 1) ? av[i].y
                            : (kk == 2) ? av[i].z : av[i].w;
                    ULL ap = pack2(a);
                    fma2(acc[i][0], ap, wA.x);
                    fma2(acc[i][1], ap, wA.y);
                    fma2(acc[i][2], ap, wB.x);
                    fma2(acc[i][3], ap, wB.y);
                }
            }
        }

        // epilogue: STS to padded tile (+ global C for scan3)
        float* sT = isB ? sB : sC;
        #pragma unroll
        for (int i = 0; i < 4; i++) {
            int t = tbase + tg + 8*i;
            ulonglong2 q0 = make_ulonglong2(acc[i][0], acc[i][1]);
            ulonglong2 q1 = make_ulonglong2(acc[i][2], acc[i][3]);
            *(ulonglong2*)&sT[t*68 + colbase + cx*8]     = q0;
            *(ulonglong2*)&sT[t*68 + colbase + cx*8 + 4] = q1;
            if (!isB) {
                float* gp = g_C + (bT + t0c + t)*64 + colbase + cx*8;
                *(ulonglong2*)(gp)     = q0;
                *(ulonglong2*)(gp + 4) = q1;
            }
        }
    }

    // ---- V-GEMM + sd/du: thread owns (t = tid>>2, heads ho*4..ho*4+3) ----
    {
        int tV = tid >> 2, ho = tid & 3;
        float s0[4] = {0.f, 0.f, 0.f, 0.f};
        #pragma unroll 4
        for (int k = 0; k < 64; k++) {
            float a = sO[tV*68 + k];
            float4 v0 = *(const float4*)&sV[k*16 + ho*4];
            s0[0] = fmaf(a, v0.x, s0[0]); s0[1] = fmaf(a, v0.y, s0[1]);
            s0[2] = fmaf(a, v0.z, s0[2]); s0[3] = fmaf(a, v0.w, s0[3]);
        }
        float4 wd4 = __ldg((const float4*)(W_dt    + ho*4));
        float4 bs4 = __ldg((const float4*)(dt_bias + ho*4));
        float4 al4 = __ldg((const float4*)(A_log   + ho*4));
        float4 dv4 = __ldg((const float4*)(Dv      + ho*4));
        float wd[4] = {wd4.x, wd4.y, wd4.z, wd4.w};
        float bs[4] = {bs4.x, bs4.y, bs4.z, bs4.w};
        float al[4] = {al4.x, al4.y, al4.z, al4.w};
        float dv[4] = {dv4.x, dv4.y, dv4.z, dv4.w};
        float rw = sRw[tV];
        float sv[4], dc[4], du[4];
        #pragma unroll
        for (int j = 0; j < 4; j++) {
            float x  = fmaf(rw, wd[j], bs[j]);
            float dt = fmaxf(x, 0.f) + __logf(1.f + __expf(-fabsf(x)));
            dc[j] = __expf(dt * (-__expf(al[j])));
            sv[j] = dt * s0[j];
            du[j] = dv[j] * s0[j];
        }
        *(float4*)&sS[tV*16 + ho*4]   = make_float4(sv[0], sv[1], sv[2], sv[3]);
        *(float4*)&sDec[tV*16 + ho*4] = make_float4(dc[0], dc[1], dc[2], dc[3]);
        *(float4*)&sDu[tV*16 + ho*4]  = make_float4(du[0], du[1], du[2], du[3]);
    }
    __syncthreads();

    // ---- scan: warps 0-3 only; warp hg owns heads hg*4..+3, lane owns
    //      n-pair {2*lane, 2*lane+1} (packed). No cross-warp exchange. ----
    if (w < 4) {
        int hg   = w;
        int n0   = 2*lane;
        int myj  = lane >> 3;          // which of the 4 heads this lane outputs
        int myq  = lane & 7;           // which timestep within the window
        int hOwn = hg*4 + myj;

        ULL gA = 0ull, gB2 = 0ull, gC2 = 0ull, gD = 0ull;
        float Dcar = 1.f;

        for (int win = 0; win < 8; win++) {
            float yv[32];
            float Dl = 1.f;
            #pragma unroll
            for (int q = 0; q < 8; q++) {
                int t = win*8 + q;
                ULL bv = *(const ULL*)&sB[t*68 + n0];
                ULL cv = *(const ULL*)&sC[t*68 + n0];
                float4 s4 = *(const float4*)&sS[t*16 + hg*4];
                float4 d4 = *(const float4*)&sDec[t*16 + hg*4];
                ULL u0, u1, u2, u3;
                mul2(u0, pack2(s4.x), bv); fma2(u0, gA,  pack2(d4.x)); gA  = u0;
                mul2(u1, pack2(s4.y), bv); fma2(u1, gB2, pack2(d4.y)); gB2 = u1;
                mul2(u2, pack2(s4.z), bv); fma2(u2, gC2, pack2(d4.z)); gC2 = u2;
                mul2(u3, pack2(s4.w), bv); fma2(u3, gD,  pack2(d4.w)); gD  = u3;
                ULL y0, y1, y2, y3;
                mul2(y0, gA,  cv); mul2(y1, gB2, cv);
                mul2(y2, gC2, cv); mul2(y3, gD,  cv);
                float2 f0 = unpack2(y0), f1 = unpack2(y1);
                float2 f2 = unpack2(y2), f3 = unpack2(y3);
                yv[q]      = f0.x + f0.y;
                yv[8 + q]  = f1.x + f1.y;
                yv[16 + q] = f2.x + f2.y;
                yv[24 + q] = f3.x + f3.y;
                float dOwn = sDec[t*16 + hOwn];
                if (q <= myq) Dl *= dOwn;
            }
            // 32-lane transposed butterfly: lane L ends with the 64-n sum for
            // (h = hg*4 + (L>>3), t = win*8 + (L&7))
            #pragma unroll
            for (int s = 16; s >= 1; s >>= 1) {
                bool hi = (lane & s) != 0;
                #pragma unroll
                for (int j = 0; j < s; j++) {
                    float snd = hi ? yv[j] : yv[j + s];
                    float rcv = __shfl_xor_sync(0xffffffffu, snd, s);
                    yv[j] = (hi ? yv[j + s] : yv[j]) + rcv;
                }
            }
            int t = win*8 + myq;
            float du = sDu[t*16 + hOwn];
            g_yD[(bT + t0c + t)*16 + hOwn] = make_float2(yv[0] + du, Dcar * Dl);
            float Dfull = __shfl_sync(0xffffffffu, Dl, (lane & 24) | 7);
            Dcar *= Dfull;
        }

        // chunk-final states (packed n-pairs)
        int e = ((c*64 + b)*16 + hg*4)*64 + n0;
        *(float2*)&g_end[e]       = unpack2(gA);
        *(float2*)&g_end[e + 64]  = unpack2(gB2);
        *(float2*)&g_end[e + 128] = unpack2(gC2);
        *(float2*)&g_end[e + 192] = unpack2(gD);
    }
}

// ---------------------------------------------------------------------------
// scan2: stitch 32 chunk initial states per (b,h). Ring prefetch (depth 4).
// ---------------------------------------------------------------------------
__global__ void scan2_kernel() {
    int chain = blockIdx.x * 8 + (threadIdx.x >> 5);
    int lane  = threadIdx.x & 31;
    int h = chain & 15, b = chain >> 4;

    float g1 = g_g0[h*64 + lane];
    float g2 = g_g0[h*64 + lane + 32];
    int gi0 = ((0*64 + b)*16 + h)*64;
    g_init[gi0 + lane]      = g1;
    g_init[gi0 + lane + 32] = g2;

    float P[NC-1];
    #pragma unroll
    for (int j = 0; j < NC-1; j++)
        P[j] = g_yD[((size_t)b*T_ + (j+1)*CH - 1)*16 + h].y;

    float e1[4], e2[4];
    #pragma unroll
    for (int j = 0; j < 4; j++) {
        int e = ((j*64 + b)*16 + h)*64;
        e1[j] = g_end[e + lane];
        e2[j] = g_end[e + lane + 32];
    }

    #pragma unroll
    for (int c = 1; c < NC; c++) {
        int s = (c-1) & 3;
        g1 = fmaf(g1, P[c-1], e1[s]);
        g2 = fmaf(g2, P[c-1], e2[s]);
        int gio = ((c*64 + b)*16 + h)*64;
        g_init[gio + lane]      = g1;
        g_init[gio + lane + 32] = g2;
        int jn = c + 3;
        if (jn <= NC-2) {
            int e = ((jn*64 + b)*16 + h)*64;
            e1[s] = g_end[e + lane];
            e2[s] = g_end[e + lane + 32];
        }
    }
}

// ---------------------------------------------------------------------------
// scan3: correction + head-sum + output. Block per (b,chunk), 8 warps x 8 t.
// Factored inner loop: w[n] = sum_h D_h*gi[h][n] (packed fma2), then one
// packed dot with the C pair (single LDG.64). Software-pipelined loads.
// ---------------------------------------------------------------------------
__global__ void scan3_kernel(float* __restrict__ out, int out_size) {
    int b = blockIdx.x & 63, c = blockIdx.x >> 6;
    int lane = threadIdx.x & 31;
    int w    = threadIdx.x >> 5;
    int n0   = 2*lane;

    ULL gi[16];
    #pragma unroll
    for (int h = 0; h < 16; h++) {
        int giOff = ((c*64 + b)*16 + h)*64;
        gi[h] = *(const ULL*)&g_init[giOff + n0];
    }

    size_t bT = (size_t)b*T_;
    int tbase = c*CH + w*8;

    // prologue: load row 0
    ULL cv = *(const ULL*)&g_C[(bT + tbase)*64 + n0];
    float2 yD = make_float2(0.f, 0.f);
    if (lane < 16) yD = g_yD[(bT + tbase)*16 + lane];

    #pragma unroll
    for (int q = 0; q < 8; q++) {
        // prefetch next row before computing this one
        ULL cvn = 0ull;
        float2 yDn = make_float2(0.f, 0.f);
        if (q < 7) {
            size_t rn = bT + tbase + q + 1;
            cvn = *(const ULL*)&g_C[rn*64 + n0];
            if (lane < 16) yDn = g_yD[rn*16 + lane];
        }

        // w[n-pair] = sum_h D_h * gi[h]
        ULL wP = 0ull;
        #pragma unroll
        for (int h = 0; h < 16; h++) {
            float Dh = __shfl_sync(0xffffffffu, yD.y, h);
            fma2(wP, pack2(Dh), gi[h]);
        }
        ULL aP; mul2(aP, wP, cv);
        float2 af = unpack2(aP);
        float acc = yD.x + af.x + af.y;   // yD.x nonzero only on lanes 0..15
        acc += __shfl_xor_sync(0xffffffffu, acc, 16);
        acc += __shfl_xor_sync(0xffffffffu, acc, 8);
        acc += __shfl_xor_sync(0xffffffffu, acc, 4);
        acc += __shfl_xor_sync(0xffffffffu, acc, 2);
        acc += __shfl_xor_sync(0xffffffffu, acc, 1);
        if (lane == 0) {
            int idx = (tbase + q)*64 + b;
            for (int j = idx; j < out_size; j += TB) out[j] = acc;
        }
        cv = cvn; yD = yDn;
    }
}

// ---------------------------------------------------------------------------
extern "C" void kernel_launch(void* const* d_in, const int* in_sizes, int n_in,
                              void* d_out, int out_size) {
    const float* obs     = (const float*)d_in[0];
    const float* reward  = (const float*)d_in[1];
    const float* W_in    = (const float*)d_in[2];
    const float* W_B     = (const float*)d_in[3];
    const float* W_C     = (const float*)d_in[4];
    const float* W_dt    = (const float*)d_in[5];
    const float* dt_b    = (const float*)d_in[6];
    const float* A_log   = (const float*)d_in[7];
    const float* Dv      = (const float*)d_in[8];
    const float* W_out   = (const float*)d_in[9];
    const float* init    = (const float*)d_in[10];
    float* out = (float*)d_out;

    cudaFuncSetAttribute(mega_kernel,
                         cudaFuncAttributeMaxDynamicSharedMemorySize, MEGA_SMEM);

    prep_kernel<<<8, 256>>>(W_in, W_out, init);
    mega_kernel<<<BK*NC, 256, MEGA_SMEM>>>(obs, reward, W_B, W_C,
                                           W_dt, dt_b, A_log, Dv);
    scan2_kernel<<<BK*H_/8, 256>>>();
    scan3_kernel<<<BK*NC, 256>>>(out, out_size);
}